// round 16
// baseline (speedup 1.0000x reference)
#include <cuda_runtime.h>
#include <cuda_bf16.h>
#include <cstdint>

#define BB 8
#define NN 2048
#define DD 128
#define SHIFT 20.0f

// ---------------- scratch (static device globals; no allocation) ----------------
__device__ float g_H[BB * NN * DD];                 // 8 MB
__device__ float g_G[BB * NN * DD];                 // 8 MB
__device__ float g_colsum[BB * NN];
__device__ __nv_bfloat16 g_Shi[(size_t)BB * NN * 256];   // 8 MB  (split [H|G])
__device__ __nv_bfloat16 g_Slo[(size_t)BB * NN * 256];   // 8 MB
__device__ __nv_bfloat16 g_Phi[(size_t)BB * NN * NN];    // 67 MB (split P)
__device__ __nv_bfloat16 g_Plo[(size_t)BB * NN * NN];    // 67 MB
__device__ __nv_bfloat16 g_Thi[(size_t)BB * DD * NN];    // 4 MB  (split H^T * inv)
__device__ __nv_bfloat16 g_Tlo[(size_t)BB * DD * NN];    // 4 MB

// ================= warp MMA / async helpers (plain PTX, sm_80+) =================
__device__ __forceinline__ uint32_t smem_u32(const void* p) {
    uint32_t a;
    asm("{ .reg .u64 t; cvta.to.shared.u64 t, %1; cvt.u32.u64 %0, t; }" : "=r"(a) : "l"(p));
    return a;
}
__device__ __forceinline__ void ldsm_x4(uint32_t& r0, uint32_t& r1, uint32_t& r2, uint32_t& r3,
                                        uint32_t addr) {
    asm volatile("ldmatrix.sync.aligned.m8n8.x4.shared.b16 {%0,%1,%2,%3}, [%4];"
                 : "=r"(r0), "=r"(r1), "=r"(r2), "=r"(r3) : "r"(addr));
}
__device__ __forceinline__ void mma16816(float* d, const uint32_t* a, uint32_t b0, uint32_t b1) {
    asm volatile(
        "mma.sync.aligned.m16n8k16.row.col.f32.bf16.bf16.f32 "
        "{%0,%1,%2,%3}, {%4,%5,%6,%7}, {%8,%9}, {%0,%1,%2,%3};"
        : "+f"(d[0]), "+f"(d[1]), "+f"(d[2]), "+f"(d[3])
        : "r"(a[0]), "r"(a[1]), "r"(a[2]), "r"(a[3]), "r"(b0), "r"(b1));
}
__device__ __forceinline__ void cp_async16(uint32_t dst, const void* src) {
    asm volatile("cp.async.cg.shared.global [%0], [%1], 16;" :: "r"(dst), "l"(src));
}
#define CP_COMMIT() asm volatile("cp.async.commit_group;" ::: "memory")
#define CP_WAIT(n)  asm volatile("cp.async.wait_group %0;" :: "n"(n) : "memory")

// ---------------- K1: C[r,c] = X[r,128] @ W[128,128] (+bias) ----------------
__global__ __launch_bounds__(256) void gemm_k(const float* __restrict__ Xin,
                                              const float* __restrict__ W,
                                              const float* __restrict__ bias,
                                              int mode)
{
    __shared__ float Xs[16][68];
    __shared__ float Ws[16][128];
    const float* X = mode ? g_H : Xin;
    float* C = mode ? g_G : g_H;

    int tid = threadIdx.x;
    int tx = tid & 15, ty = tid >> 4;
    int r0 = blockIdx.x * 64;

    float acc[4][8];
#pragma unroll
    for (int i = 0; i < 4; i++)
#pragma unroll
        for (int j = 0; j < 8; j++) acc[i][j] = 0.f;

    for (int k0 = 0; k0 < 128; k0 += 16) {
        {
            int row = tid >> 2, c4 = tid & 3;
            float4 v = *(const float4*)(X + (size_t)(r0 + row) * DD + k0 + c4 * 4);
            Xs[c4 * 4 + 0][row] = v.x; Xs[c4 * 4 + 1][row] = v.y;
            Xs[c4 * 4 + 2][row] = v.z; Xs[c4 * 4 + 3][row] = v.w;
        }
#pragma unroll
        for (int it = 0; it < 2; it++) {
            int f = tid + it * 256; int kk = f >> 5, c4 = f & 31;
            *(float4*)(&Ws[kk][c4 * 4]) = *(const float4*)(W + (size_t)(k0 + kk) * DD + c4 * 4);
        }
        __syncthreads();
#pragma unroll
        for (int kk = 0; kk < 16; kk++) {
            float a[4], bv[8];
#pragma unroll
            for (int i = 0; i < 4; i++) a[i] = Xs[kk][ty * 4 + i];
#pragma unroll
            for (int j = 0; j < 8; j++) bv[j] = Ws[kk][tx + 16 * j];
#pragma unroll
            for (int i = 0; i < 4; i++)
#pragma unroll
                for (int j = 0; j < 8; j++) acc[i][j] += a[i] * bv[j];
        }
        __syncthreads();
    }

    float bj[8];
#pragma unroll
    for (int j = 0; j < 8; j++) bj[j] = bias ? bias[tx + 16 * j] : 0.f;
#pragma unroll
    for (int i = 0; i < 4; i++) {
        int r = r0 + ty * 4 + i;
#pragma unroll
        for (int j = 0; j < 8; j++) {
            int c = tx + 16 * j;
            C[(size_t)r * DD + c] = acc[i][j] + bj[j];
        }
    }
}

// ---------------- split H,G into bf16 hi/lo; also zero colsum ----------------
__global__ __launch_bounds__(128) void split_k()
{
    int row = blockIdx.x;
    int t = threadIdx.x;
    if (t == 0) g_colsum[row] = 0.f;
    float h = g_H[(size_t)row * DD + t];
    float g = g_G[(size_t)row * DD + t];
    __nv_bfloat16 hh = __float2bfloat16(h);
    __nv_bfloat16 gh = __float2bfloat16(g);
    size_t base = (size_t)row * 256;
    g_Shi[base + t]       = hh;
    g_Slo[base + t]       = __float2bfloat16(h - __bfloat162float(hh));
    g_Shi[base + 128 + t] = gh;
    g_Slo[base + 128 + t] = __float2bfloat16(g - __bfloat162float(gh));
}

// ---------------- K2: score kernel, symmetric, triangular grid, cp.async ----------------
#define KC 32
#define LDS_STRIDE 40
#define ARR_BYTES (128 * LDS_STRIDE * 2)     // 10240
#define STAGE_BYTES (4 * ARR_BYTES)          // 40960
#define OFF_A0 0
#define OFF_A1 ARR_BYTES
#define OFF_B0 (2 * ARR_BYTES)
#define OFF_B1 (3 * ARR_BYTES)

__global__ __launch_bounds__(256, 2) void score_k(const float* __restrict__ adj)
{
    extern __shared__ char dynsmem[];
    uint32_t sdyn = smem_u32(dynsmem);

    // triangular decode (CORRECT): t -> (by, bx), bx >= by, row lengths 16,15,...,1
    int by = 0, rem = blockIdx.x;
    while (rem >= 16 - by) { rem -= 16 - by; by++; }
    int bx = by + rem;

    int tid = threadIdx.x;
    int wid = tid >> 5, lane = tid & 31;
    int gid = lane >> 2, tig = lane & 3;

    int m0 = bx * 128;
    int n0 = by * 128;
    int b  = blockIdx.z;

    int mw = (wid >> 2) * 64;
    int nw = (wid & 3) * 32;

    float acc[2][8][4];
#pragma unroll
    for (int i = 0; i < 2; i++)
#pragma unroll
        for (int j = 0; j < 8; j++)
#pragma unroll
            for (int k = 0; k < 4; k++) acc[i][j][k] = 0.f;

    int aRow = lane & 15,                       aKof = (lane >> 4) << 3;
    int bRow = (lane & 7) + ((lane >> 4) << 3), bKof = ((lane >> 3) & 1) << 3;

    int lrow0 = tid >> 2,         lseg0 = tid & 3;
    int lrow1 = (tid + 256) >> 2, lseg1 = (tid + 256) & 3;
    uint32_t soff0 = (uint32_t)(lrow0 * (LDS_STRIDE * 2) + lseg0 * 16);
    uint32_t soff1 = (uint32_t)(lrow1 * (LDS_STRIDE * 2) + lseg1 * 16);

    auto issue_chunk = [&](int c, int s) {
        size_t baseN = ((size_t)b * NN + n0) * 256 + (size_t)(c * KC);
        size_t baseM = ((size_t)b * NN + m0) * 256 + (size_t)(((c + 4) & 7) * KC);
        uint32_t sb = sdyn + s * STAGE_BYTES;
        size_t gn0 = baseN + (size_t)lrow0 * 256 + lseg0 * 8;
        size_t gn1 = baseN + (size_t)lrow1 * 256 + lseg1 * 8;
        size_t gm0 = baseM + (size_t)lrow0 * 256 + lseg0 * 8;
        size_t gm1 = baseM + (size_t)lrow1 * 256 + lseg1 * 8;
        cp_async16(sb + OFF_A0 + soff0, g_Shi + gn0);
        cp_async16(sb + OFF_A0 + soff1, g_Shi + gn1);
        cp_async16(sb + OFF_A1 + soff0, g_Slo + gn0);
        cp_async16(sb + OFF_A1 + soff1, g_Slo + gn1);
        cp_async16(sb + OFF_B0 + soff0, g_Shi + gm0);
        cp_async16(sb + OFF_B0 + soff1, g_Shi + gm1);
        cp_async16(sb + OFF_B1 + soff0, g_Slo + gm0);
        cp_async16(sb + OFF_B1 + soff1, g_Slo + gm1);
    };

    issue_chunk(0, 0);
    CP_COMMIT();

    for (int c = 0; c < 8; ++c) {
        int s = c & 1;
        if (c + 1 < 8) { issue_chunk(c + 1, s ^ 1); CP_COMMIT(); }
        if (c + 1 < 8) CP_WAIT(1); else CP_WAIT(0);
        __syncthreads();

        uint32_t sb = sdyn + s * STAGE_BYTES;
        uint32_t aNhi = sb + OFF_A0, aNlo = sb + OFF_A1;
        uint32_t aMhi = sb + OFF_B0, aMlo = sb + OFF_B1;

#pragma unroll
        for (int ks = 0; ks < 2; ks++) {
            int k0 = ks * 16;
            uint32_t aHi[2][4], aLo[2][4];
#pragma unroll
            for (int nf = 0; nf < 2; nf++) {
                uint32_t off = (uint32_t)(((nw + nf * 16 + aRow) * LDS_STRIDE + k0 + aKof) * 2);
                ldsm_x4(aHi[nf][0], aHi[nf][1], aHi[nf][2], aHi[nf][3], aNhi + off);
                ldsm_x4(aLo[nf][0], aLo[nf][1], aLo[nf][2], aLo[nf][3], aNlo + off);
            }
            uint32_t bFr[4][4];
#pragma unroll
            for (int bi = 0; bi < 4; bi++) {
                uint32_t off = (uint32_t)(((mw + bi * 16 + bRow) * LDS_STRIDE + k0 + bKof) * 2);
                ldsm_x4(bFr[bi][0], bFr[bi][1], bFr[bi][2], bFr[bi][3], aMhi + off);
            }
#pragma unroll
            for (int nf = 0; nf < 2; nf++)
#pragma unroll
                for (int mf = 0; mf < 8; mf++) {
                    uint32_t b0 = bFr[mf >> 1][(mf & 1) ? 2 : 0];
                    uint32_t b1 = bFr[mf >> 1][(mf & 1) ? 3 : 1];
                    mma16816(acc[nf][mf], aHi[nf], b0, b1);
                    mma16816(acc[nf][mf], aLo[nf], b0, b1);
                }
#pragma unroll
            for (int bi = 0; bi < 4; bi++) {
                uint32_t off = (uint32_t)(((mw + bi * 16 + bRow) * LDS_STRIDE + k0 + bKof) * 2);
                ldsm_x4(bFr[bi][0], bFr[bi][1], bFr[bi][2], bFr[bi][3], aMlo + off);
            }
#pragma unroll
            for (int nf = 0; nf < 2; nf++)
#pragma unroll
                for (int mf = 0; mf < 8; mf++) {
                    uint32_t b0 = bFr[mf >> 1][(mf & 1) ? 2 : 0];
                    uint32_t b1 = bFr[mf >> 1][(mf & 1) ? 3 : 1];
                    mma16816(acc[nf][mf], aHi[nf], b0, b1);
                }
        }
        __syncthreads();
    }

    // ---- exp once, in place ----
#pragma unroll
    for (int i = 0; i < 2; i++)
#pragma unroll
        for (int j = 0; j < 8; j++)
#pragma unroll
            for (int k = 0; k < 4; k++)
                acc[i][j][k] = __expf(acc[i][j][k] - SHIFT);

    // ---- normal tile: P[n,m] = adj[n,m]*ex ; colsum[m] ----
    float cs0[8], cs1[8];
#pragma unroll
    for (int mf = 0; mf < 8; mf++) { cs0[mf] = 0.f; cs1[mf] = 0.f; }

#pragma unroll
    for (int nf = 0; nf < 2; nf++) {
#pragma unroll
        for (int half = 0; half < 2; half++) {
            int n = n0 + nw + nf * 16 + gid + half * 8;
            const float2* arow = (const float2*)(adj + ((size_t)b * NN + n) * NN + m0);
            __nv_bfloat162* ph = (__nv_bfloat162*)(g_Phi + ((size_t)b * NN + n) * NN + m0);
            __nv_bfloat162* pl = (__nv_bfloat162*)(g_Plo + ((size_t)b * NN + n) * NN + m0);
#pragma unroll
            for (int mf = 0; mf < 8; mf++) {
                int moff2 = (mw + mf * 8 + tig * 2) >> 1;
                float2 a2 = __ldg(arow + moff2);
                float p0 = a2.x * acc[nf][mf][half * 2 + 0];
                float p1 = a2.y * acc[nf][mf][half * 2 + 1];
                __nv_bfloat16 h0 = __float2bfloat16(p0);
                __nv_bfloat16 h1 = __float2bfloat16(p1);
                ph[moff2] = __nv_bfloat162(h0, h1);
                pl[moff2] = __nv_bfloat162(
                    __float2bfloat16(p0 - __bfloat162float(h0)),
                    __float2bfloat16(p1 - __bfloat162float(h1)));
                cs0[mf] += p0;
                cs1[mf] += p1;
            }
        }
    }
#pragma unroll
    for (int mf = 0; mf < 8; mf++) {
#pragma unroll
        for (int d = 4; d < 32; d <<= 1) {
            cs0[mf] += __shfl_xor_sync(0xFFFFFFFF, cs0[mf], d);
            cs1[mf] += __shfl_xor_sync(0xFFFFFFFF, cs1[mf], d);
        }
        if (lane < 4) {
            int m = m0 + mw + mf * 8 + lane * 2;
            atomicAdd(&g_colsum[b * NN + m],     cs0[mf]);
            atomicAdd(&g_colsum[b * NN + m + 1], cs1[mf]);
        }
    }

    // ---- mirror tile (off-diagonal only): smem-staged, coalesced ----
    if (bx != by) {
        float* PT = (float*)dynsmem;     // [128][132] fp32 = 67.6 KB (stages dead)
#pragma unroll
        for (int nf = 0; nf < 2; nf++)
#pragma unroll
            for (int mf = 0; mf < 8; mf++)
#pragma unroll
                for (int k = 0; k < 4; k++) {
                    int nloc = nw + nf * 16 + (k >> 1) * 8 + gid;
                    int mloc = mw + mf * 8 + tig * 2 + (k & 1);
                    PT[mloc * 132 + nloc] = acc[nf][mf][k];
                }
        __syncthreads();
        int ncol = tid & 127;
        int mstart = (tid >> 7) * 64;
        float csn = 0.f;
        for (int mi = 0; mi < 64; mi++) {
            int mloc = mstart + mi;
            size_t grow = ((size_t)b * NN + m0 + mloc) * NN + n0 + ncol;
            float ex = PT[mloc * 132 + ncol];
            float a = __ldg(adj + grow);
            float p = a * ex;
            __nv_bfloat16 hp = __float2bfloat16(p);
            g_Phi[grow] = hp;
            g_Plo[grow] = __float2bfloat16(p - __bfloat162float(hp));
            csn += p;
        }
        __syncthreads();
        PT[tid] = csn;
        __syncthreads();
        if (tid < 128)
            atomicAdd(&g_colsum[b * NN + n0 + tid], PT[tid] + PT[tid + 128]);
    }
}

// ---------------- transpose + scale + split (inv fused): T[d][m] = H[m][d]/colsum[m] ----------------
__global__ __launch_bounds__(256) void transpose_k()
{
    __shared__ float t[32][33];
    int m0 = blockIdx.x * 32, d0 = blockIdx.y * 32, b = blockIdx.z;
    int tx = threadIdx.x & 31, ty = threadIdx.x >> 5;

#pragma unroll
    for (int i = ty; i < 32; i += 8) {
        float s = g_colsum[b * NN + m0 + i];
        float inv = (s > 0.f) ? 1.f / s : 0.f;
        t[i][tx] = g_H[((size_t)b * NN + m0 + i) * DD + d0 + tx] * inv;
    }
    __syncthreads();
#pragma unroll
    for (int i = ty; i < 32; i += 8) {
        float v = t[tx][i];
        __nv_bfloat16 hi = __float2bfloat16(v);
        size_t o = ((size_t)b * DD + d0 + i) * NN + m0 + tx;
        g_Thi[o] = hi;
        g_Tlo[o] = __float2bfloat16(v - __bfloat162float(hi));
    }
}

// ---------------- K3: h' = P @ T^T, 64-row n-tile, cp.async double-buffered ----------------
#define OARR_A (64 * LDS_STRIDE * 2)         // 5120
#define OARR_B (128 * LDS_STRIDE * 2)        // 10240
#define OSTAGE (2 * OARR_A + 2 * OARR_B)     // 30720
#define O_PA0 0
#define O_PA1 OARR_A
#define O_TB0 (2 * OARR_A)
#define O_TB1 (2 * OARR_A + OARR_B)

__global__ __launch_bounds__(256, 2) void outmma_k(const float* __restrict__ x,
                                                   const float* __restrict__ gate_w,
                                                   const float* __restrict__ gate_b,
                                                   float* __restrict__ out)
{
    extern __shared__ char dynsmem[];
    uint32_t sdyn = smem_u32(dynsmem);
    __shared__ float gws[256];
    __shared__ float sred[2][64];
    __shared__ float coef[64];

    int tid = threadIdx.x;
    int wid = tid >> 5, lane = tid & 31;
    int gid = lane >> 2, tig = lane & 3;

    int n0 = blockIdx.x * 64;
    int b  = blockIdx.y;

    int mw = (wid >> 2) * 64;     // d-offset (2 warps)
    int mwid = wid >> 2;
    int nw = (wid & 3) * 16;      // n-offset (4 warps x 16 rows)

    gws[tid] = gate_w[tid];

    float acc[8][4];
#pragma unroll
    for (int j = 0; j < 8; j++)
#pragma unroll
        for (int k = 0; k < 4; k++) acc[j][k] = 0.f;

    int aRow = lane & 15,                       aKof = (lane >> 4) << 3;
    int bRow = (lane & 7) + ((lane >> 4) << 3), bKof = ((lane >> 3) & 1) << 3;

    size_t basePn = ((size_t)b * NN + n0) * NN;
    size_t baseTd = (size_t)b * DD * NN;

    int lrowA = tid >> 2,          lsegA = tid & 3;
    int lrow0 = tid >> 2,          lseg0 = tid & 3;
    int lrow1 = (tid + 256) >> 2,  lseg1 = (tid + 256) & 3;
    uint32_t soffA = (uint32_t)(lrowA * (LDS_STRIDE * 2) + lsegA * 16);
    uint32_t soff0 = (uint32_t)(lrow0 * (LDS_STRIDE * 2) + lseg0 * 16);
    uint32_t soff1 = (uint32_t)(lrow1 * (LDS_STRIDE * 2) + lseg1 * 16);

    auto issue_chunk = [&](int c, int s) {
        int mc = c * KC;
        uint32_t sb = sdyn + s * OSTAGE;
        size_t gp = basePn + (size_t)lrowA * NN + mc + lsegA * 8;
        size_t gt0 = baseTd + (size_t)lrow0 * NN + mc + lseg0 * 8;
        size_t gt1 = baseTd + (size_t)lrow1 * NN + mc + lseg1 * 8;
        cp_async16(sb + O_PA0 + soffA, g_Phi + gp);
        cp_async16(sb + O_PA1 + soffA, g_Plo + gp);
        cp_async16(sb + O_TB0 + soff0, g_Thi + gt0);
        cp_async16(sb + O_TB0 + soff1, g_Thi + gt1);
        cp_async16(sb + O_TB1 + soff0, g_Tlo + gt0);
        cp_async16(sb + O_TB1 + soff1, g_Tlo + gt1);
    };

    issue_chunk(0, 0);
    CP_COMMIT();

    for (int c = 0; c < NN / KC; ++c) {
        int s = c & 1;
        if (c + 1 < NN / KC) { issue_chunk(c + 1, s ^ 1); CP_COMMIT(); }
        if (c + 1 < NN / KC) CP_WAIT(1); else CP_WAIT(0);
        __syncthreads();

        uint32_t sb = sdyn + s * OSTAGE;
        uint32_t aPhi = sb + O_PA0, aPlo = sb + O_PA1;
        uint32_t aThi = sb + O_TB0, aTlo = sb + O_TB1;

#pragma unroll
        for (int ks = 0; ks < 2; ks++) {
            int k0 = ks * 16;
            uint32_t aHi[4], aLo[4];
            {
                uint32_t off = (uint32_t)(((nw + aRow) * LDS_STRIDE + k0 + aKof) * 2);
                ldsm_x4(aHi[0], aHi[1], aHi[2], aHi[3], aPhi + off);
                ldsm_x4(aLo[0], aLo[1], aLo[2], aLo[3], aPlo + off);
            }
            uint32_t bFr[4][4];
#pragma unroll
            for (int bi = 0; bi < 4; bi++) {
                uint32_t off = (uint32_t)(((mw + bi * 16 + bRow) * LDS_STRIDE + k0 + bKof) * 2);
                ldsm_x4(bFr[bi][0], bFr[bi][1], bFr[bi][2], bFr[bi][3], aThi + off);
            }
#pragma unroll
            for (int mf = 0; mf < 8; mf++) {
                uint32_t b0 = bFr[mf >> 1][(mf & 1) ? 2 : 0];
                uint32_t b1 = bFr[mf >> 1][(mf & 1) ? 3 : 1];
                mma16816(acc[mf], aHi, b0, b1);
                mma16816(acc[mf], aLo, b0, b1);
            }
#pragma unroll
            for (int bi = 0; bi < 4; bi++) {
                uint32_t off = (uint32_t)(((mw + bi * 16 + bRow) * LDS_STRIDE + k0 + bKof) * 2);
                ldsm_x4(bFr[bi][0], bFr[bi][1], bFr[bi][2], bFr[bi][3], aTlo + off);
            }
#pragma unroll
            for (int mf = 0; mf < 8; mf++) {
                uint32_t b0 = bFr[mf >> 1][(mf & 1) ? 2 : 0];
                uint32_t b1 = bFr[mf >> 1][(mf & 1) ? 3 : 1];
                mma16816(acc[mf], aHi, b0, b1);
            }
        }
        __syncthreads();
    }

    // ---------------- epilogue: relu, gate dot, sigmoid, mix ----------------
#pragma unroll
    for (int half = 0; half < 2; half++) {
        int nloc = nw + gid + half * 8;
        int n = n0 + nloc;
        const float2* xrow = (const float2*)(x + ((size_t)b * NN + n) * DD);
        float partial = 0.f;
#pragma unroll
        for (int mf = 0; mf < 8; mf++) {
            int d = mw + mf * 8 + tig * 2;
            float2 x2 = __ldg(xrow + (d >> 1));
            float hp0 = fmaxf(acc[mf][half * 2 + 0], 0.f);
            float hp1 = fmaxf(acc[mf][half * 2 + 1], 0.f);
            acc[mf][half * 2 + 0] = hp0;
            acc[mf][half * 2 + 1] = hp1;
            partial += x2.x * gws[d] + x2.y * gws[d + 1]
                     + hp0 * gws[128 + d] + hp1 * gws[128 + d + 1];
        }
        partial += __shfl_xor_sync(0xFFFFFFFF, partial, 1);
        partial += __shfl_xor_sync(0xFFFFFFFF, partial, 2);
        if (tig == 0) sred[mwid][nloc] = partial;
    }
    __syncthreads();
    if (tid < 64) {
        float s = sred[0][tid] + sred[1][tid] + gate_b[0];
        coef[tid] = 1.f / (1.f + __expf(-s));
    }
    __syncthreads();

#pragma unroll
    for (int half = 0; half < 2; half++) {
        int nloc = nw + gid + half * 8;
        int n = n0 + nloc;
        float cf = coef[nloc];
        const float2* xrow = (const float2*)(x + ((size_t)b * NN + n) * DD);
        float2* orow = (float2*)(out + ((size_t)b * NN + n) * DD);
#pragma unroll
        for (int mf = 0; mf < 8; mf++) {
            int d = mw + mf * 8 + tig * 2;
            float2 x2 = __ldg(xrow + (d >> 1));
            float hp0 = acc[mf][half * 2 + 0];
            float hp1 = acc[mf][half * 2 + 1];
            orow[d >> 1] = make_float2(cf * x2.x + (1.f - cf) * hp0,
                                       cf * x2.y + (1.f - cf) * hp1);
        }
    }
}

// ---------------- launch ----------------
extern "C" void kernel_launch(void* const* d_in, const int* in_sizes, int n_in,
                              void* d_out, int out_size)
{
    const float* x      = (const float*)d_in[0];
    const float* adj    = (const float*)d_in[1];
    const float* W_w    = (const float*)d_in[2];
    const float* W_b    = (const float*)d_in[3];
    const float* A_w    = (const float*)d_in[4];
    const float* gate_w = (const float*)d_in[5];
    const float* gate_b = (const float*)d_in[6];
    float* out = (float*)d_out;

    cudaFuncSetAttribute(score_k,  cudaFuncAttributeMaxDynamicSharedMemorySize, 2 * STAGE_BYTES);
    cudaFuncSetAttribute(outmma_k, cudaFuncAttributeMaxDynamicSharedMemorySize, 2 * OSTAGE);

    gemm_k<<<BB * NN / 64, 256>>>(x, W_w, W_b, 0);            // g_H = xW + b
    gemm_k<<<BB * NN / 64, 256>>>(nullptr, A_w, nullptr, 1);  // g_G = g_H A
    split_k<<<BB * NN, 128>>>();                              // bf16 hi/lo + zero colsum
    score_k<<<dim3(136, 1, BB), 256, 2 * STAGE_BYTES>>>(adj); // triangular grid (fixed decode)
    transpose_k<<<dim3(NN / 32, DD / 32, BB), 256>>>();       // Thi/Tlo (inv fused)
    outmma_k<<<dim3(NN / 64, BB), 256, 2 * OSTAGE>>>(x, gate_w, gate_b, out);
}

// round 17
// speedup vs baseline: 1.1155x; 1.1155x over previous
#include <cuda_runtime.h>
#include <cuda_bf16.h>
#include <cuda_fp16.h>
#include <cstdint>

#define BB 8
#define NN 2048
#define DD 128
#define SHIFT 20.0f

// ---------------- scratch (static device globals; no allocation) ----------------
__device__ float g_H[BB * NN * DD];                 // 8 MB
__device__ float g_G[BB * NN * DD];                 // 8 MB
__device__ float g_colsum[BB * NN];
__device__ __half g_Shi[(size_t)BB * NN * 256];          // 8 MB  (fp16 split [H|G])
__device__ __half g_Slo[(size_t)BB * NN * 256];          // 8 MB
__device__ __nv_bfloat16 g_Phi[(size_t)BB * NN * NN];    // 67 MB (bf16 split P — range!)
__device__ __nv_bfloat16 g_Plo[(size_t)BB * NN * NN];    // 67 MB
__device__ __nv_bfloat16 g_Thi[(size_t)BB * DD * NN];    // 4 MB  (bf16 split H^T * inv)
__device__ __nv_bfloat16 g_Tlo[(size_t)BB * DD * NN];    // 4 MB

// ================= warp MMA / async helpers (plain PTX, sm_80+) =================
__device__ __forceinline__ uint32_t smem_u32(const void* p) {
    uint32_t a;
    asm("{ .reg .u64 t; cvta.to.shared.u64 t, %1; cvt.u32.u64 %0, t; }" : "=r"(a) : "l"(p));
    return a;
}
__device__ __forceinline__ void ldsm_x4(uint32_t& r0, uint32_t& r1, uint32_t& r2, uint32_t& r3,
                                        uint32_t addr) {
    asm volatile("ldmatrix.sync.aligned.m8n8.x4.shared.b16 {%0,%1,%2,%3}, [%4];"
                 : "=r"(r0), "=r"(r1), "=r"(r2), "=r"(r3) : "r"(addr));
}
__device__ __forceinline__ void mma16816(float* d, const uint32_t* a, uint32_t b0, uint32_t b1) {
    asm volatile(
        "mma.sync.aligned.m16n8k16.row.col.f32.bf16.bf16.f32 "
        "{%0,%1,%2,%3}, {%4,%5,%6,%7}, {%8,%9}, {%0,%1,%2,%3};"
        : "+f"(d[0]), "+f"(d[1]), "+f"(d[2]), "+f"(d[3])
        : "r"(a[0]), "r"(a[1]), "r"(a[2]), "r"(a[3]), "r"(b0), "r"(b1));
}
__device__ __forceinline__ void mma16816h(float* d, const uint32_t* a, uint32_t b0, uint32_t b1) {
    asm volatile(
        "mma.sync.aligned.m16n8k16.row.col.f32.f16.f16.f32 "
        "{%0,%1,%2,%3}, {%4,%5,%6,%7}, {%8,%9}, {%0,%1,%2,%3};"
        : "+f"(d[0]), "+f"(d[1]), "+f"(d[2]), "+f"(d[3])
        : "r"(a[0]), "r"(a[1]), "r"(a[2]), "r"(a[3]), "r"(b0), "r"(b1));
}
__device__ __forceinline__ void cp_async16(uint32_t dst, const void* src) {
    asm volatile("cp.async.cg.shared.global [%0], [%1], 16;" :: "r"(dst), "l"(src));
}
#define CP_COMMIT() asm volatile("cp.async.commit_group;" ::: "memory")
#define CP_WAIT(n)  asm volatile("cp.async.wait_group %0;" :: "n"(n) : "memory")

// ---------------- K1: C[r,c] = X[r,128] @ W[128,128] (+bias) ----------------
__global__ __launch_bounds__(256) void gemm_k(const float* __restrict__ Xin,
                                              const float* __restrict__ W,
                                              const float* __restrict__ bias,
                                              int mode)
{
    __shared__ float Xs[16][68];
    __shared__ float Ws[16][128];
    const float* X = mode ? g_H : Xin;
    float* C = mode ? g_G : g_H;

    int tid = threadIdx.x;
    int tx = tid & 15, ty = tid >> 4;
    int r0 = blockIdx.x * 64;

    float acc[4][8];
#pragma unroll
    for (int i = 0; i < 4; i++)
#pragma unroll
        for (int j = 0; j < 8; j++) acc[i][j] = 0.f;

    for (int k0 = 0; k0 < 128; k0 += 16) {
        {
            int row = tid >> 2, c4 = tid & 3;
            float4 v = *(const float4*)(X + (size_t)(r0 + row) * DD + k0 + c4 * 4);
            Xs[c4 * 4 + 0][row] = v.x; Xs[c4 * 4 + 1][row] = v.y;
            Xs[c4 * 4 + 2][row] = v.z; Xs[c4 * 4 + 3][row] = v.w;
        }
#pragma unroll
        for (int it = 0; it < 2; it++) {
            int f = tid + it * 256; int kk = f >> 5, c4 = f & 31;
            *(float4*)(&Ws[kk][c4 * 4]) = *(const float4*)(W + (size_t)(k0 + kk) * DD + c4 * 4);
        }
        __syncthreads();
#pragma unroll
        for (int kk = 0; kk < 16; kk++) {
            float a[4], bv[8];
#pragma unroll
            for (int i = 0; i < 4; i++) a[i] = Xs[kk][ty * 4 + i];
#pragma unroll
            for (int j = 0; j < 8; j++) bv[j] = Ws[kk][tx + 16 * j];
#pragma unroll
            for (int i = 0; i < 4; i++)
#pragma unroll
                for (int j = 0; j < 8; j++) acc[i][j] += a[i] * bv[j];
        }
        __syncthreads();
    }

    float bj[8];
#pragma unroll
    for (int j = 0; j < 8; j++) bj[j] = bias ? bias[tx + 16 * j] : 0.f;
#pragma unroll
    for (int i = 0; i < 4; i++) {
        int r = r0 + ty * 4 + i;
#pragma unroll
        for (int j = 0; j < 8; j++) {
            int c = tx + 16 * j;
            C[(size_t)r * DD + c] = acc[i][j] + bj[j];
        }
    }
}

// ---------------- split H,G into fp16 hi/lo; also zero colsum ----------------
__global__ __launch_bounds__(128) void split_k()
{
    int row = blockIdx.x;
    int t = threadIdx.x;
    if (t == 0) g_colsum[row] = 0.f;
    float h = g_H[(size_t)row * DD + t];
    float g = g_G[(size_t)row * DD + t];
    __half hh = __float2half_rn(h);
    __half gh = __float2half_rn(g);
    size_t base = (size_t)row * 256;
    g_Shi[base + t]       = hh;
    g_Slo[base + t]       = __float2half_rn(h - __half2float(hh));
    g_Shi[base + 128 + t] = gh;
    g_Slo[base + 128 + t] = __float2half_rn(g - __half2float(gh));
}

// ---------------- K2: score, symmetric, triangular, fp16 2-pass, cp.async ----------------
#define KC 32
#define LDS_STRIDE 40
#define ARR_BYTES (128 * LDS_STRIDE * 2)     // 10240
// score stage: 3 arrays (Nhi, Nlo, Mhi)
#define S_STAGE (3 * ARR_BYTES)              // 30720
#define S_DYN   (128 * 132 * 4)              // 67584 (mirror PT; >= 2*S_STAGE)
#define SOFF_NHI 0
#define SOFF_NLO ARR_BYTES
#define SOFF_MHI (2 * ARR_BYTES)

__global__ __launch_bounds__(256, 2) void score_k(const float* __restrict__ adj)
{
    extern __shared__ char dynsmem[];
    uint32_t sdyn = smem_u32(dynsmem);

    // triangular decode: t -> (by, bx), bx >= by, row lengths 16,15,...,1
    int by = 0, rem = blockIdx.x;
    while (rem >= 16 - by) { rem -= 16 - by; by++; }
    int bx = by + rem;

    int tid = threadIdx.x;
    int wid = tid >> 5, lane = tid & 31;
    int gid = lane >> 2, tig = lane & 3;

    int m0 = bx * 128;
    int n0 = by * 128;
    int b  = blockIdx.z;

    int mw = (wid >> 2) * 64;
    int nw = (wid & 3) * 32;

    float acc[2][8][4];
#pragma unroll
    for (int i = 0; i < 2; i++)
#pragma unroll
        for (int j = 0; j < 8; j++)
#pragma unroll
            for (int k = 0; k < 4; k++) acc[i][j][k] = 0.f;

    int aRow = lane & 15,                       aKof = (lane >> 4) << 3;
    int bRow = (lane & 7) + ((lane >> 4) << 3), bKof = ((lane >> 3) & 1) << 3;

    int lrow0 = tid >> 2,         lseg0 = tid & 3;
    int lrow1 = (tid + 256) >> 2, lseg1 = (tid + 256) & 3;
    uint32_t soff0 = (uint32_t)(lrow0 * (LDS_STRIDE * 2) + lseg0 * 16);
    uint32_t soff1 = (uint32_t)(lrow1 * (LDS_STRIDE * 2) + lseg1 * 16);

    auto issue_chunk = [&](int c, int s) {
        size_t baseN = ((size_t)b * NN + n0) * 256 + (size_t)(c * KC);
        size_t baseM = ((size_t)b * NN + m0) * 256 + (size_t)(((c + 4) & 7) * KC);
        uint32_t sb = sdyn + s * S_STAGE;
        size_t gn0 = baseN + (size_t)lrow0 * 256 + lseg0 * 8;
        size_t gn1 = baseN + (size_t)lrow1 * 256 + lseg1 * 8;
        size_t gm0 = baseM + (size_t)lrow0 * 256 + lseg0 * 8;
        size_t gm1 = baseM + (size_t)lrow1 * 256 + lseg1 * 8;
        cp_async16(sb + SOFF_NHI + soff0, g_Shi + gn0);
        cp_async16(sb + SOFF_NHI + soff1, g_Shi + gn1);
        cp_async16(sb + SOFF_NLO + soff0, g_Slo + gn0);
        cp_async16(sb + SOFF_NLO + soff1, g_Slo + gn1);
        cp_async16(sb + SOFF_MHI + soff0, g_Shi + gm0);
        cp_async16(sb + SOFF_MHI + soff1, g_Shi + gm1);
    };

    issue_chunk(0, 0);
    CP_COMMIT();

    for (int c = 0; c < 8; ++c) {
        int s = c & 1;
        if (c + 1 < 8) { issue_chunk(c + 1, s ^ 1); CP_COMMIT(); }
        if (c + 1 < 8) CP_WAIT(1); else CP_WAIT(0);
        __syncthreads();

        uint32_t sb = sdyn + s * S_STAGE;
        uint32_t aNhi = sb + SOFF_NHI, aNlo = sb + SOFF_NLO;
        uint32_t aMhi = sb + SOFF_MHI;

#pragma unroll
        for (int ks = 0; ks < 2; ks++) {
            int k0 = ks * 16;
            uint32_t aHi[2][4], aLo[2][4];
#pragma unroll
            for (int nf = 0; nf < 2; nf++) {
                uint32_t off = (uint32_t)(((nw + nf * 16 + aRow) * LDS_STRIDE + k0 + aKof) * 2);
                ldsm_x4(aHi[nf][0], aHi[nf][1], aHi[nf][2], aHi[nf][3], aNhi + off);
                ldsm_x4(aLo[nf][0], aLo[nf][1], aLo[nf][2], aLo[nf][3], aNlo + off);
            }
            uint32_t bFr[4][4];
#pragma unroll
            for (int bi = 0; bi < 4; bi++) {
                uint32_t off = (uint32_t)(((mw + bi * 16 + bRow) * LDS_STRIDE + k0 + bKof) * 2);
                ldsm_x4(bFr[bi][0], bFr[bi][1], bFr[bi][2], bFr[bi][3], aMhi + off);
            }
            // pass0: Nhi x Mhi ; pass1: Nlo x Mhi  (Mlo term dropped: ~2^-12 rel)
#pragma unroll
            for (int nf = 0; nf < 2; nf++)
#pragma unroll
                for (int mf = 0; mf < 8; mf++) {
                    uint32_t b0 = bFr[mf >> 1][(mf & 1) ? 2 : 0];
                    uint32_t b1 = bFr[mf >> 1][(mf & 1) ? 3 : 1];
                    mma16816h(acc[nf][mf], aHi[nf], b0, b1);
                    mma16816h(acc[nf][mf], aLo[nf], b0, b1);
                }
        }
        __syncthreads();
    }

    // ---- exp once, in place ----
#pragma unroll
    for (int i = 0; i < 2; i++)
#pragma unroll
        for (int j = 0; j < 8; j++)
#pragma unroll
            for (int k = 0; k < 4; k++)
                acc[i][j][k] = __expf(acc[i][j][k] - SHIFT);

    // ---- normal tile: P[n,m] = adj[n,m]*ex ; colsum[m] ----
    float cs0[8], cs1[8];
#pragma unroll
    for (int mf = 0; mf < 8; mf++) { cs0[mf] = 0.f; cs1[mf] = 0.f; }

#pragma unroll
    for (int nf = 0; nf < 2; nf++) {
#pragma unroll
        for (int half = 0; half < 2; half++) {
            int n = n0 + nw + nf * 16 + gid + half * 8;
            const float2* arow = (const float2*)(adj + ((size_t)b * NN + n) * NN + m0);
            __nv_bfloat162* ph = (__nv_bfloat162*)(g_Phi + ((size_t)b * NN + n) * NN + m0);
            __nv_bfloat162* pl = (__nv_bfloat162*)(g_Plo + ((size_t)b * NN + n) * NN + m0);
#pragma unroll
            for (int mf = 0; mf < 8; mf++) {
                int moff2 = (mw + mf * 8 + tig * 2) >> 1;
                float2 a2 = __ldg(arow + moff2);
                float p0 = a2.x * acc[nf][mf][half * 2 + 0];
                float p1 = a2.y * acc[nf][mf][half * 2 + 1];
                __nv_bfloat16 h0 = __float2bfloat16(p0);
                __nv_bfloat16 h1 = __float2bfloat16(p1);
                ph[moff2] = __nv_bfloat162(h0, h1);
                pl[moff2] = __nv_bfloat162(
                    __float2bfloat16(p0 - __bfloat162float(h0)),
                    __float2bfloat16(p1 - __bfloat162float(h1)));
                cs0[mf] += p0;
                cs1[mf] += p1;
            }
        }
    }
#pragma unroll
    for (int mf = 0; mf < 8; mf++) {
#pragma unroll
        for (int d = 4; d < 32; d <<= 1) {
            cs0[mf] += __shfl_xor_sync(0xFFFFFFFF, cs0[mf], d);
            cs1[mf] += __shfl_xor_sync(0xFFFFFFFF, cs1[mf], d);
        }
        if (lane < 4) {
            int m = m0 + mw + mf * 8 + lane * 2;
            atomicAdd(&g_colsum[b * NN + m],     cs0[mf]);
            atomicAdd(&g_colsum[b * NN + m + 1], cs1[mf]);
        }
    }

    // ---- mirror tile (off-diagonal only): smem-staged, coalesced ----
    if (bx != by) {
        float* PT = (float*)dynsmem;     // [128][132] fp32 = 67584 B (stages dead)
#pragma unroll
        for (int nf = 0; nf < 2; nf++)
#pragma unroll
            for (int mf = 0; mf < 8; mf++)
#pragma unroll
                for (int k = 0; k < 4; k++) {
                    int nloc = nw + nf * 16 + (k >> 1) * 8 + gid;
                    int mloc = mw + mf * 8 + tig * 2 + (k & 1);
                    PT[mloc * 132 + nloc] = acc[nf][mf][k];
                }
        __syncthreads();
        int ncol = tid & 127;
        int mstart = (tid >> 7) * 64;
        float csn = 0.f;
        for (int mi = 0; mi < 64; mi++) {
            int mloc = mstart + mi;
            size_t grow = ((size_t)b * NN + m0 + mloc) * NN + n0 + ncol;
            float ex = PT[mloc * 132 + ncol];
            float a = __ldg(adj + grow);
            float p = a * ex;
            __nv_bfloat16 hp = __float2bfloat16(p);
            g_Phi[grow] = hp;
            g_Plo[grow] = __float2bfloat16(p - __bfloat162float(hp));
            csn += p;
        }
        __syncthreads();
        PT[tid] = csn;
        __syncthreads();
        if (tid < 128)
            atomicAdd(&g_colsum[b * NN + n0 + tid], PT[tid] + PT[tid + 128]);
    }
}

// ---------------- transpose + scale + split (inv fused): T[d][m] = H[m][d]/colsum[m] ----------------
__global__ __launch_bounds__(256) void transpose_k()
{
    __shared__ float t[32][33];
    int m0 = blockIdx.x * 32, d0 = blockIdx.y * 32, b = blockIdx.z;
    int tx = threadIdx.x & 31, ty = threadIdx.x >> 5;

#pragma unroll
    for (int i = ty; i < 32; i += 8) {
        float s = g_colsum[b * NN + m0 + i];
        float inv = (s > 0.f) ? 1.f / s : 0.f;
        t[i][tx] = g_H[((size_t)b * NN + m0 + i) * DD + d0 + tx] * inv;
    }
    __syncthreads();
#pragma unroll
    for (int i = ty; i < 32; i += 8) {
        float v = t[tx][i];
        __nv_bfloat16 hi = __float2bfloat16(v);
        size_t o = ((size_t)b * DD + d0 + i) * NN + m0 + tx;
        g_Thi[o] = hi;
        g_Tlo[o] = __float2bfloat16(v - __bfloat162float(hi));
    }
}

// ---------------- K3: h' = P @ T^T, 128-row n-tile (R14), cp.async double-buffered ----------------
#define STAGE_BYTES (4 * ARR_BYTES)          // 40960
#define OFF_A0 0
#define OFF_A1 ARR_BYTES
#define OFF_B0 (2 * ARR_BYTES)
#define OFF_B1 (3 * ARR_BYTES)

__global__ __launch_bounds__(256, 2) void outmma_k(const float* __restrict__ x,
                                                   const float* __restrict__ gate_w,
                                                   const float* __restrict__ gate_b,
                                                   float* __restrict__ out)
{
    extern __shared__ char dynsmem[];
    uint32_t sdyn = smem_u32(dynsmem);
    __shared__ float gws[256];
    __shared__ float sred[2][128];
    __shared__ float coef[128];

    int tid = threadIdx.x;
    int wid = tid >> 5, lane = tid & 31;
    int gid = lane >> 2, tig = lane & 3;

    int n0 = blockIdx.x * 128;
    int b  = blockIdx.y;

    int mw = (wid >> 2) * 64;
    int mwid = wid >> 2;
    int nw = (wid & 3) * 32;

    gws[tid] = gate_w[tid];

    float acc[2][8][4];
#pragma unroll
    for (int i = 0; i < 2; i++)
#pragma unroll
        for (int j = 0; j < 8; j++)
#pragma unroll
            for (int k = 0; k < 4; k++) acc[i][j][k] = 0.f;

    int aRow = lane & 15,                       aKof = (lane >> 4) << 3;
    int bRow = (lane & 7) + ((lane >> 4) << 3), bKof = ((lane >> 3) & 1) << 3;

    size_t basePn = ((size_t)b * NN + n0) * NN;
    size_t baseTd = (size_t)b * DD * NN;

    int lrow0 = tid >> 2,         lseg0 = tid & 3;
    int lrow1 = (tid + 256) >> 2, lseg1 = (tid + 256) & 3;
    uint32_t soff0 = (uint32_t)(lrow0 * (LDS_STRIDE * 2) + lseg0 * 16);
    uint32_t soff1 = (uint32_t)(lrow1 * (LDS_STRIDE * 2) + lseg1 * 16);

    auto issue_chunk = [&](int c, int s) {
        int mc = c * KC;
        uint32_t sb = sdyn + s * STAGE_BYTES;
        size_t gp0 = basePn + (size_t)lrow0 * NN + mc + lseg0 * 8;
        size_t gp1 = basePn + (size_t)lrow1 * NN + mc + lseg1 * 8;
        size_t gt0 = baseTd + (size_t)lrow0 * NN + mc + lseg0 * 8;
        size_t gt1 = baseTd + (size_t)lrow1 * NN + mc + lseg1 * 8;
        cp_async16(sb + OFF_A0 + soff0, g_Phi + gp0);
        cp_async16(sb + OFF_A0 + soff1, g_Phi + gp1);
        cp_async16(sb + OFF_A1 + soff0, g_Plo + gp0);
        cp_async16(sb + OFF_A1 + soff1, g_Plo + gp1);
        cp_async16(sb + OFF_B0 + soff0, g_Thi + gt0);
        cp_async16(sb + OFF_B0 + soff1, g_Thi + gt1);
        cp_async16(sb + OFF_B1 + soff0, g_Tlo + gt0);
        cp_async16(sb + OFF_B1 + soff1, g_Tlo + gt1);
    };

    issue_chunk(0, 0);
    CP_COMMIT();

    for (int c = 0; c < NN / KC; ++c) {
        int s = c & 1;
        if (c + 1 < NN / KC) { issue_chunk(c + 1, s ^ 1); CP_COMMIT(); }
        if (c + 1 < NN / KC) CP_WAIT(1); else CP_WAIT(0);
        __syncthreads();

        uint32_t sb = sdyn + s * STAGE_BYTES;
        uint32_t aPhi = sb + OFF_A0, aPlo = sb + OFF_A1;
        uint32_t aThi = sb + OFF_B0, aTlo = sb + OFF_B1;

#pragma unroll
        for (int ks = 0; ks < 2; ks++) {
            int k0 = ks * 16;
            uint32_t aHi[2][4], aLo[2][4];
#pragma unroll
            for (int nf = 0; nf < 2; nf++) {
                uint32_t off = (uint32_t)(((nw + nf * 16 + aRow) * LDS_STRIDE + k0 + aKof) * 2);
                ldsm_x4(aHi[nf][0], aHi[nf][1], aHi[nf][2], aHi[nf][3], aPhi + off);
                ldsm_x4(aLo[nf][0], aLo[nf][1], aLo[nf][2], aLo[nf][3], aPlo + off);
            }
            uint32_t bFr[4][4];
#pragma unroll
            for (int bi = 0; bi < 4; bi++) {
                uint32_t off = (uint32_t)(((mw + bi * 16 + bRow) * LDS_STRIDE + k0 + bKof) * 2);
                ldsm_x4(bFr[bi][0], bFr[bi][1], bFr[bi][2], bFr[bi][3], aThi + off);
            }
#pragma unroll
            for (int nf = 0; nf < 2; nf++)
#pragma unroll
                for (int mf = 0; mf < 8; mf++) {
                    uint32_t b0 = bFr[mf >> 1][(mf & 1) ? 2 : 0];
                    uint32_t b1 = bFr[mf >> 1][(mf & 1) ? 3 : 1];
                    mma16816(acc[nf][mf], aHi[nf], b0, b1);
                    mma16816(acc[nf][mf], aLo[nf], b0, b1);
                }
#pragma unroll
            for (int bi = 0; bi < 4; bi++) {
                uint32_t off = (uint32_t)(((mw + bi * 16 + bRow) * LDS_STRIDE + k0 + bKof) * 2);
                ldsm_x4(bFr[bi][0], bFr[bi][1], bFr[bi][2], bFr[bi][3], aTlo + off);
            }
#pragma unroll
            for (int nf = 0; nf < 2; nf++)
#pragma unroll
                for (int mf = 0; mf < 8; mf++) {
                    uint32_t b0 = bFr[mf >> 1][(mf & 1) ? 2 : 0];
                    uint32_t b1 = bFr[mf >> 1][(mf & 1) ? 3 : 1];
                    mma16816(acc[nf][mf], aHi[nf], b0, b1);
                }
        }
        __syncthreads();
    }

    // ---------------- epilogue: relu, gate dot, sigmoid, mix ----------------
#pragma unroll
    for (int nf = 0; nf < 2; nf++) {
#pragma unroll
        for (int half = 0; half < 2; half++) {
            int nloc = nw + nf * 16 + gid + half * 8;
            int n = n0 + nloc;
            const float2* xrow = (const float2*)(x + ((size_t)b * NN + n) * DD);
            float partial = 0.f;
#pragma unroll
            for (int mf = 0; mf < 8; mf++) {
                int d = mw + mf * 8 + tig * 2;
                float2 x2 = __ldg(xrow + (d >> 1));
                float hp0 = fmaxf(acc[nf][mf][half * 2 + 0], 0.f);
                float hp1 = fmaxf(acc[nf][mf][half * 2 + 1], 0.f);
                acc[nf][mf][half * 2 + 0] = hp0;
                acc[nf][mf][half * 2 + 1] = hp1;
                partial += x2.x * gws[d] + x2.y * gws[d + 1]
                         + hp0 * gws[128 + d] + hp1 * gws[128 + d + 1];
            }
            partial += __shfl_xor_sync(0xFFFFFFFF, partial, 1);
            partial += __shfl_xor_sync(0xFFFFFFFF, partial, 2);
            if (tig == 0) sred[mwid][nloc] = partial;
        }
    }
    __syncthreads();
    if (tid < 128) {
        float s = sred[0][tid] + sred[1][tid] + gate_b[0];
        coef[tid] = 1.f / (1.f + __expf(-s));
    }
    __syncthreads();

#pragma unroll
    for (int nf = 0; nf < 2; nf++) {
#pragma unroll
        for (int half = 0; half < 2; half++) {
            int nloc = nw + nf * 16 + gid + half * 8;
            int n = n0 + nloc;
            float cf = coef[nloc];
            const float2* xrow = (const float2*)(x + ((size_t)b * NN + n) * DD);
            float2* orow = (float2*)(out + ((size_t)b * NN + n) * DD);
#pragma unroll
            for (int mf = 0; mf < 8; mf++) {
                int d = mw + mf * 8 + tig * 2;
                float2 x2 = __ldg(xrow + (d >> 1));
                float hp0 = acc[nf][mf][half * 2 + 0];
                float hp1 = acc[nf][mf][half * 2 + 1];
                orow[d >> 1] = make_float2(cf * x2.x + (1.f - cf) * hp0,
                                           cf * x2.y + (1.f - cf) * hp1);
            }
        }
    }
}

// ---------------- launch ----------------
extern "C" void kernel_launch(void* const* d_in, const int* in_sizes, int n_in,
                              void* d_out, int out_size)
{
    const float* x      = (const float*)d_in[0];
    const float* adj    = (const float*)d_in[1];
    const float* W_w    = (const float*)d_in[2];
    const float* W_b    = (const float*)d_in[3];
    const float* A_w    = (const float*)d_in[4];
    const float* gate_w = (const float*)d_in[5];
    const float* gate_b = (const float*)d_in[6];
    float* out = (float*)d_out;

    cudaFuncSetAttribute(score_k,  cudaFuncAttributeMaxDynamicSharedMemorySize, S_DYN);
    cudaFuncSetAttribute(outmma_k, cudaFuncAttributeMaxDynamicSharedMemorySize, 2 * STAGE_BYTES);

    gemm_k<<<BB * NN / 64, 256>>>(x, W_w, W_b, 0);            // g_H = xW + b
    gemm_k<<<BB * NN / 64, 256>>>(nullptr, A_w, nullptr, 1);  // g_G = g_H A
    split_k<<<BB * NN, 128>>>();                              // fp16 hi/lo + zero colsum
    score_k<<<dim3(136, 1, BB), 256, S_DYN>>>(adj);           // triangular, fp16 2-pass
    transpose_k<<<dim3(NN / 32, DD / 32, BB), 256>>>();       // Thi/Tlo (inv fused)
    outmma_k<<<dim3(NN / 128, BB), 256, 2 * STAGE_BYTES>>>(x, gate_w, gate_b, out);
}